// round 1
// baseline (speedup 1.0000x reference)
#include <cuda_runtime.h>
#include <cuda_bf16.h>
#include <cstdint>

// ---------------------------------------------------------------------------
// GraphConvolution: out = segment_sum( (X@W)[edge_src] * edge_val, edge_dst )
//   X: [50000, 512] f32, W: [512, 128] f32, edges: 800000 (edge_dst sorted)
// Stage 1: SGEMM  support = X @ W          (fp32, 128x128x16 tiles, 8x8 uT)
// Stage 2: rowptr[i] = lower_bound(edge_dst, i)   (binary search per node)
// Stage 3: warp-per-node segment sum over edge range (no atomics)
// ---------------------------------------------------------------------------

#define MAX_NODES 50000
#define D_IN      512
#define D_OUT     128

// Scratch (no cudaMalloc allowed): device globals.
__device__ float g_support[(size_t)MAX_NODES * D_OUT];
__device__ int   g_rowptr[MAX_NODES + 1];

// ---------------------------------------------------------------------------
// Stage 1: SGEMM 128x128 block, BK=16, 256 threads, 8x8 microtile (split 4+4)
// ---------------------------------------------------------------------------
#define BM 128
#define BN 128
#define BK 16

__global__ __launch_bounds__(256, 2)
void gemm_kernel(const float* __restrict__ X, const float* __restrict__ W, int M)
{
    __shared__ float Xs[BK][BM];   // transposed: Xs[k][m]
    __shared__ float Ws[BK][BN];   // Ws[k][n]

    const int tid = threadIdx.x;
    const int tx  = tid & 15;        // 16 column groups
    const int ty  = tid >> 4;        // 16 row groups
    const int rowBase = blockIdx.x * BM;

    // split-tile coordinates: rows {ty*4..+3} U {64+ty*4..+3}, cols likewise
    const int rA = ty * 4;
    const int rB = 64 + ty * 4;
    const int cA = tx * 4;
    const int cB = 64 + tx * 4;

    float acc[8][8];
#pragma unroll
    for (int i = 0; i < 8; i++)
#pragma unroll
        for (int j = 0; j < 8; j++) acc[i][j] = 0.f;

    for (int k0 = 0; k0 < D_IN; k0 += BK) {
        // --- load X tile (128 rows x 16 k) as float4, store transposed ---
#pragma unroll
        for (int it = 0; it < 2; it++) {
            int f  = tid * 2 + it;          // 0..511 float4s
            int r  = f >> 2;                // 0..127 (tile row)
            int c4 = (f & 3) * 4;           // 0,4,8,12 (k offset)
            int grow = rowBase + r;
            float4 v;
            if (grow < M)
                v = *reinterpret_cast<const float4*>(&X[(size_t)grow * D_IN + k0 + c4]);
            else
                v = make_float4(0.f, 0.f, 0.f, 0.f);
            Xs[c4 + 0][r] = v.x;
            Xs[c4 + 1][r] = v.y;
            Xs[c4 + 2][r] = v.z;
            Xs[c4 + 3][r] = v.w;
        }
        // --- load W tile (16 k x 128 n) ---
#pragma unroll
        for (int it = 0; it < 2; it++) {
            int f  = tid * 2 + it;          // 0..511 float4s
            int r  = f >> 5;                // 0..15  (k)
            int c4 = (f & 31) * 4;          // 0..124 (n)
            float4 v = *reinterpret_cast<const float4*>(&W[(size_t)(k0 + r) * D_OUT + c4]);
            *reinterpret_cast<float4*>(&Ws[r][c4]) = v;
        }
        __syncthreads();

#pragma unroll
        for (int k = 0; k < BK; k++) {
            float a[8], b[8];
            *reinterpret_cast<float4*>(&a[0]) = *reinterpret_cast<const float4*>(&Xs[k][rA]);
            *reinterpret_cast<float4*>(&a[4]) = *reinterpret_cast<const float4*>(&Xs[k][rB]);
            *reinterpret_cast<float4*>(&b[0]) = *reinterpret_cast<const float4*>(&Ws[k][cA]);
            *reinterpret_cast<float4*>(&b[4]) = *reinterpret_cast<const float4*>(&Ws[k][cB]);
#pragma unroll
            for (int i = 0; i < 8; i++)
#pragma unroll
                for (int j = 0; j < 8; j++)
                    acc[i][j] = fmaf(a[i], b[j], acc[i][j]);
        }
        __syncthreads();
    }

    // --- epilogue: write support ---
#pragma unroll
    for (int i = 0; i < 8; i++) {
        int r = rowBase + ((i < 4) ? (rA + i) : (rB + i - 4));
        if (r < M) {
            float4 v0 = make_float4(acc[i][0], acc[i][1], acc[i][2], acc[i][3]);
            float4 v1 = make_float4(acc[i][4], acc[i][5], acc[i][6], acc[i][7]);
            *reinterpret_cast<float4*>(&g_support[(size_t)r * D_OUT + cA]) = v0;
            *reinterpret_cast<float4*>(&g_support[(size_t)r * D_OUT + cB]) = v1;
        }
    }
}

// ---------------------------------------------------------------------------
// Stage 2: rowptr[i] = lower_bound(edge_dst, i); rowptr[M] = E
// ---------------------------------------------------------------------------
__global__ void rowptr_kernel(const int* __restrict__ edge_dst, int E, int M)
{
    int i = blockIdx.x * blockDim.x + threadIdx.x;
    if (i > M) return;
    int lo = 0, hi = E;
    while (lo < hi) {
        int mid = (lo + hi) >> 1;
        if (edge_dst[mid] < i) lo = mid + 1; else hi = mid;
    }
    g_rowptr[i] = lo;
}

// ---------------------------------------------------------------------------
// Stage 3: warp per node: acc[128] (4 f32/lane) over sorted edge range
// ---------------------------------------------------------------------------
__global__ __launch_bounds__(256)
void spmm_kernel(const int* __restrict__ edge_src,
                 const float* __restrict__ edge_val,
                 float* __restrict__ out, int M)
{
    const int warp = threadIdx.x >> 5;
    const int lane = threadIdx.x & 31;
    const int node = blockIdx.x * 8 + warp;
    if (node >= M) return;

    const int s = g_rowptr[node];
    const int e = g_rowptr[node + 1];

    float4 acc = make_float4(0.f, 0.f, 0.f, 0.f);
    const int col = lane * 4;

    int i = s;
    // 4x unroll for memory-level parallelism (gathers hit L2: support resident)
    for (; i + 3 < e; i += 4) {
        int s0 = edge_src[i + 0], s1 = edge_src[i + 1];
        int s2 = edge_src[i + 2], s3 = edge_src[i + 3];
        float v0 = edge_val[i + 0], v1 = edge_val[i + 1];
        float v2 = edge_val[i + 2], v3 = edge_val[i + 3];
        float4 g0 = *reinterpret_cast<const float4*>(&g_support[(size_t)s0 * D_OUT + col]);
        float4 g1 = *reinterpret_cast<const float4*>(&g_support[(size_t)s1 * D_OUT + col]);
        float4 g2 = *reinterpret_cast<const float4*>(&g_support[(size_t)s2 * D_OUT + col]);
        float4 g3 = *reinterpret_cast<const float4*>(&g_support[(size_t)s3 * D_OUT + col]);
        acc.x = fmaf(g0.x, v0, acc.x); acc.y = fmaf(g0.y, v0, acc.y);
        acc.z = fmaf(g0.z, v0, acc.z); acc.w = fmaf(g0.w, v0, acc.w);
        acc.x = fmaf(g1.x, v1, acc.x); acc.y = fmaf(g1.y, v1, acc.y);
        acc.z = fmaf(g1.z, v1, acc.z); acc.w = fmaf(g1.w, v1, acc.w);
        acc.x = fmaf(g2.x, v2, acc.x); acc.y = fmaf(g2.y, v2, acc.y);
        acc.z = fmaf(g2.z, v2, acc.z); acc.w = fmaf(g2.w, v2, acc.w);
        acc.x = fmaf(g3.x, v3, acc.x); acc.y = fmaf(g3.y, v3, acc.y);
        acc.z = fmaf(g3.z, v3, acc.z); acc.w = fmaf(g3.w, v3, acc.w);
    }
    for (; i < e; ++i) {
        int sr = edge_src[i];
        float v = edge_val[i];
        float4 g = *reinterpret_cast<const float4*>(&g_support[(size_t)sr * D_OUT + col]);
        acc.x = fmaf(g.x, v, acc.x); acc.y = fmaf(g.y, v, acc.y);
        acc.z = fmaf(g.z, v, acc.z); acc.w = fmaf(g.w, v, acc.w);
    }

    *reinterpret_cast<float4*>(&out[(size_t)node * D_OUT + col]) = acc;
}

// ---------------------------------------------------------------------------
extern "C" void kernel_launch(void* const* d_in, const int* in_sizes, int n_in,
                              void* d_out, int out_size)
{
    const float* x        = (const float*)d_in[0];
    const int*   edge_src = (const int*)  d_in[1];
    const int*   edge_dst = (const int*)  d_in[2];
    const float* edge_val = (const float*)d_in[3];
    const float* weight   = (const float*)d_in[4];
    float*       out      = (float*)d_out;

    const int M = in_sizes[0] / D_IN;   // 50000
    const int E = in_sizes[1];          // 800000

    gemm_kernel<<<(M + BM - 1) / BM, 256>>>(x, weight, M);
    rowptr_kernel<<<(M + 1 + 255) / 256, 256>>>(edge_dst, E, M);
    spmm_kernel<<<(M + 7) / 8, 256>>>(edge_src, edge_val, out, M);
}

// round 2
// speedup vs baseline: 1.0709x; 1.0709x over previous
#include <cuda_runtime.h>
#include <cuda_bf16.h>
#include <cstdint>

// ---------------------------------------------------------------------------
// GraphConvolution: out = segment_sum( (X@W)[edge_src] * edge_val, edge_dst )
// Stage 1: SGEMM with packed fma.rn.f32x2 (FFMA2, sm_103a-only 2x fp32 FMA)
// Stage 2: rowptr via binary search (edge_dst sorted)
// Stage 3: warp-per-node segment sum (no atomics), support L2-resident
// ---------------------------------------------------------------------------

#define MAX_NODES 50000
#define D_IN      512
#define D_OUT     128

__device__ float g_support[(size_t)MAX_NODES * D_OUT];
__device__ int   g_rowptr[MAX_NODES + 1];

typedef unsigned long long u64;

// pack two fp32 into a packed f32x2 register pair
__device__ __forceinline__ u64 pack2(float lo, float hi) {
    u64 r;
    asm("mov.b64 %0, {%1, %2};" : "=l"(r) : "f"(lo), "f"(hi));
    return r;
}
// d = a * b + d   (elementwise on packed f32x2) — FFMA2, PTX-only on Blackwell
__device__ __forceinline__ void fma2(u64& d, u64 a, u64 b) {
    asm("fma.rn.f32x2 %0, %1, %2, %0;" : "+l"(d) : "l"(a), "l"(b));
}

// ---------------------------------------------------------------------------
// Stage 1: SGEMM 128x128 block, BK=16, 256 threads, 8x8 microtile (split 4+4)
// Accumulators are 32 packed f32x2 pairs (pairs along N).
// ---------------------------------------------------------------------------
#define BM 128
#define BN 128
#define BK 16

__global__ __launch_bounds__(256, 2)
void gemm_kernel(const float* __restrict__ X, const float* __restrict__ W, int M)
{
    __shared__ float Xs[BK][BM];   // transposed: Xs[k][m]
    __shared__ float Ws[BK][BN];   // Ws[k][n]

    const int tid = threadIdx.x;
    const int tx  = tid & 15;
    const int ty  = tid >> 4;
    const int rowBase = blockIdx.x * BM;

    const int rA = ty * 4;
    const int rB = 64 + ty * 4;
    const int cA = tx * 4;
    const int cB = 64 + tx * 4;

    // acc2[i][j]: row i (0..7 -> rA..rA+3, rB..rB+3), packed col pair j
    // j=0,1 -> cols cA..cA+3 ; j=2,3 -> cols cB..cB+3
    u64 acc2[8][4];
#pragma unroll
    for (int i = 0; i < 8; i++)
#pragma unroll
        for (int j = 0; j < 4; j++) acc2[i][j] = 0ULL;

    for (int k0 = 0; k0 < D_IN; k0 += BK) {
        // --- load X tile (128 rows x 16 k), store transposed ---
#pragma unroll
        for (int it = 0; it < 2; it++) {
            int f  = tid * 2 + it;
            int r  = f >> 2;
            int c4 = (f & 3) * 4;
            int grow = rowBase + r;
            float4 v;
            if (grow < M)
                v = *reinterpret_cast<const float4*>(&X[(size_t)grow * D_IN + k0 + c4]);
            else
                v = make_float4(0.f, 0.f, 0.f, 0.f);
            Xs[c4 + 0][r] = v.x;
            Xs[c4 + 1][r] = v.y;
            Xs[c4 + 2][r] = v.z;
            Xs[c4 + 3][r] = v.w;
        }
        // --- load W tile (16 k x 128 n) ---
#pragma unroll
        for (int it = 0; it < 2; it++) {
            int f  = tid * 2 + it;
            int r  = f >> 5;
            int c4 = (f & 31) * 4;
            float4 v = *reinterpret_cast<const float4*>(&W[(size_t)(k0 + r) * D_OUT + c4]);
            *reinterpret_cast<float4*>(&Ws[r][c4]) = v;
        }
        __syncthreads();

#pragma unroll
        for (int k = 0; k < BK; k++) {
            float a[8];
            *reinterpret_cast<float4*>(&a[0]) = *reinterpret_cast<const float4*>(&Xs[k][rA]);
            *reinterpret_cast<float4*>(&a[4]) = *reinterpret_cast<const float4*>(&Xs[k][rB]);
            // b column pairs: (cA,cA+1),(cA+2,cA+3),(cB,cB+1),(cB+2,cB+3)
            ulonglong2 blo = *reinterpret_cast<const ulonglong2*>(&Ws[k][cA]);
            ulonglong2 bhi = *reinterpret_cast<const ulonglong2*>(&Ws[k][cB]);
            u64 b2[4] = { blo.x, blo.y, bhi.x, bhi.y };
#pragma unroll
            for (int i = 0; i < 8; i++) {
                u64 ap = pack2(a[i], a[i]);
                fma2(acc2[i][0], ap, b2[0]);
                fma2(acc2[i][1], ap, b2[1]);
                fma2(acc2[i][2], ap, b2[2]);
                fma2(acc2[i][3], ap, b2[3]);
            }
        }
        __syncthreads();
    }

    // --- epilogue: write support (pairs are little-endian: lo = lower col) ---
#pragma unroll
    for (int i = 0; i < 8; i++) {
        int r = rowBase + ((i < 4) ? (rA + i) : (rB + i - 4));
        if (r < M) {
            ulonglong2 v0 = make_ulonglong2(acc2[i][0], acc2[i][1]);
            ulonglong2 v1 = make_ulonglong2(acc2[i][2], acc2[i][3]);
            *reinterpret_cast<ulonglong2*>(&g_support[(size_t)r * D_OUT + cA]) = v0;
            *reinterpret_cast<ulonglong2*>(&g_support[(size_t)r * D_OUT + cB]) = v1;
        }
    }
}

// ---------------------------------------------------------------------------
// Stage 2: rowptr[i] = lower_bound(edge_dst, i); rowptr[M] = E
// ---------------------------------------------------------------------------
__global__ void rowptr_kernel(const int* __restrict__ edge_dst, int E, int M)
{
    int i = blockIdx.x * blockDim.x + threadIdx.x;
    if (i > M) return;
    int lo = 0, hi = E;
    while (lo < hi) {
        int mid = (lo + hi) >> 1;
        if (edge_dst[mid] < i) lo = mid + 1; else hi = mid;
    }
    g_rowptr[i] = lo;
}

// ---------------------------------------------------------------------------
// Stage 3: warp per node: 128 cols (4 f32/lane) over sorted edge range
// ---------------------------------------------------------------------------
__global__ __launch_bounds__(256)
void spmm_kernel(const int* __restrict__ edge_src,
                 const float* __restrict__ edge_val,
                 float* __restrict__ out, int M)
{
    const int warp = threadIdx.x >> 5;
    const int lane = threadIdx.x & 31;
    const int node = blockIdx.x * 8 + warp;
    if (node >= M) return;

    const int s = g_rowptr[node];
    const int e = g_rowptr[node + 1];

    float4 acc = make_float4(0.f, 0.f, 0.f, 0.f);
    const int col = lane * 4;

    int i = s;
    for (; i + 3 < e; i += 4) {
        int s0 = edge_src[i + 0], s1 = edge_src[i + 1];
        int s2 = edge_src[i + 2], s3 = edge_src[i + 3];
        float v0 = edge_val[i + 0], v1 = edge_val[i + 1];
        float v2 = edge_val[i + 2], v3 = edge_val[i + 3];
        float4 g0 = *reinterpret_cast<const float4*>(&g_support[(size_t)s0 * D_OUT + col]);
        float4 g1 = *reinterpret_cast<const float4*>(&g_support[(size_t)s1 * D_OUT + col]);
        float4 g2 = *reinterpret_cast<const float4*>(&g_support[(size_t)s2 * D_OUT + col]);
        float4 g3 = *reinterpret_cast<const float4*>(&g_support[(size_t)s3 * D_OUT + col]);
        acc.x = fmaf(g0.x, v0, acc.x); acc.y = fmaf(g0.y, v0, acc.y);
        acc.z = fmaf(g0.z, v0, acc.z); acc.w = fmaf(g0.w, v0, acc.w);
        acc.x = fmaf(g1.x, v1, acc.x); acc.y = fmaf(g1.y, v1, acc.y);
        acc.z = fmaf(g1.z, v1, acc.z); acc.w = fmaf(g1.w, v1, acc.w);
        acc.x = fmaf(g2.x, v2, acc.x); acc.y = fmaf(g2.y, v2, acc.y);
        acc.z = fmaf(g2.z, v2, acc.z); acc.w = fmaf(g2.w, v2, acc.w);
        acc.x = fmaf(g3.x, v3, acc.x); acc.y = fmaf(g3.y, v3, acc.y);
        acc.z = fmaf(g3.z, v3, acc.z); acc.w = fmaf(g3.w, v3, acc.w);
    }
    for (; i < e; ++i) {
        int sr = edge_src[i];
        float v = edge_val[i];
        float4 g = *reinterpret_cast<const float4*>(&g_support[(size_t)sr * D_OUT + col]);
        acc.x = fmaf(g.x, v, acc.x); acc.y = fmaf(g.y, v, acc.y);
        acc.z = fmaf(g.z, v, acc.z); acc.w = fmaf(g.w, v, acc.w);
    }

    *reinterpret_cast<float4*>(&out[(size_t)node * D_OUT + col]) = acc;
}

// ---------------------------------------------------------------------------
extern "C" void kernel_launch(void* const* d_in, const int* in_sizes, int n_in,
                              void* d_out, int out_size)
{
    const float* x        = (const float*)d_in[0];
    const int*   edge_src = (const int*)  d_in[1];
    const int*   edge_dst = (const int*)  d_in[2];
    const float* edge_val = (const float*)d_in[3];
    const float* weight   = (const float*)d_in[4];
    float*       out      = (float*)d_out;

    const int M = in_sizes[0] / D_IN;   // 50000
    const int E = in_sizes[1];          // 800000

    gemm_kernel<<<(M + BM - 1) / BM, 256>>>(x, weight, M);
    rowptr_kernel<<<(M + 1 + 255) / 256, 256>>>(edge_dst, E, M);
    spmm_kernel<<<(M + 7) / 8, 256>>>(edge_src, edge_val, out, M);
}

// round 4
// speedup vs baseline: 1.5315x; 1.4302x over previous
#include <cuda_runtime.h>
#include <cuda_bf16.h>
#include <cstdint>

// ---------------------------------------------------------------------------
// GraphConvolution: out = segment_sum( (X@W)[edge_src] * edge_val, edge_dst )
// Stage 0: W f32 [k][n] -> bf16 hi/lo, transposed to [n][k]
// Stage 1: GEMM via mma.sync m16n8k16 bf16 (3-term split), plain sm_103 PTX
// Stage 2: rowptr via binary search (edge_dst sorted)
// Stage 3: warp-per-node segment sum (no atomics)
// ---------------------------------------------------------------------------

#define MAX_NODES 50000
#define D_IN      512
#define D_OUT     128
#define BK        16
#define NSTEP     (D_IN / BK)   // 32

__device__ float g_support[(size_t)MAX_NODES * D_OUT];
__device__ int   g_rowptr[MAX_NODES + 1];
__device__ __align__(16) __nv_bfloat16 g_Whi[D_OUT * D_IN]; // [n][k]
__device__ __align__(16) __nv_bfloat16 g_Wlo[D_OUT * D_IN]; // [n][k]

// ------------------------------- helpers -----------------------------------
__device__ __forceinline__ uint32_t smem_u32(const void* p) {
    uint32_t a;
    asm("{ .reg .u64 t; cvta.to.shared.u64 t, %1; cvt.u32.u64 %0, t; }"
        : "=r"(a) : "l"(p));
    return a;
}
// pack two f32 -> bf16x2 (lo = f0, hi = f1)
__device__ __forceinline__ uint32_t pack_bf2(float f0, float f1) {
    uint32_t r;
    asm("cvt.rn.bf16x2.f32 %0, %1, %2;" : "=r"(r) : "f"(f1), "f"(f0));
    return r;
}
// swizzled byte offset within a [128 rows x 32B] tile: 16B chunk XOR (row>>2)&1
__device__ __forceinline__ uint32_t swz(uint32_t r, uint32_t c) {
    return r * 32 + ((((c >> 4) ^ (r >> 2)) & 1u) << 4) + (c & 15u);
}

#define LDSM4(r0, r1, r2, r3, a) \
    asm volatile("ldmatrix.sync.aligned.m8n8.x4.shared.b16 {%0,%1,%2,%3}, [%4];" \
        : "=r"(r0), "=r"(r1), "=r"(r2), "=r"(r3) : "r"(a))
#define LDSM2(r0, r1, a) \
    asm volatile("ldmatrix.sync.aligned.m8n8.x2.shared.b16 {%0,%1}, [%2];" \
        : "=r"(r0), "=r"(r1) : "r"(a))
#define MMA16816(c, a, b) \
    asm volatile("mma.sync.aligned.m16n8k16.row.col.f32.bf16.bf16.f32 " \
        "{%0,%1,%2,%3}, {%4,%5,%6,%7}, {%8,%9}, {%0,%1,%2,%3};" \
        : "+f"((c)[0]), "+f"((c)[1]), "+f"((c)[2]), "+f"((c)[3]) \
        : "r"((a)[0]), "r"((a)[1]), "r"((a)[2]), "r"((a)[3]), \
          "r"((b)[0]), "r"((b)[1]))

// ---------------------------------------------------------------------------
// Stage 0: convert + transpose W
// ---------------------------------------------------------------------------
__global__ void convw_kernel(const float* __restrict__ W)
{
    int idx = blockIdx.x * blockDim.x + threadIdx.x;
    if (idx >= D_IN * D_OUT) return;
    int k = idx >> 7;
    int n = idx & 127;
    float f = W[idx];
    __nv_bfloat16 h = __float2bfloat16(f);
    float r = f - __bfloat162float(h);
    g_Whi[n * D_IN + k] = h;
    g_Wlo[n * D_IN + k] = __float2bfloat16(r);
}

// ---------------------------------------------------------------------------
// Stage 1: tensor-core GEMM via mma.sync (8 warps, 128x128 tile, BK=16)
// smem per buffer: Ah(4K) Al(4K) Bh(4K) Bl(4K); 2 buffers = 32KB
// ---------------------------------------------------------------------------
__global__ __launch_bounds__(256, 1)
void gemm_mma_kernel(const float* __restrict__ X, int M)
{
    __shared__ __align__(128) char sm[2][16384];

    const int tid  = threadIdx.x;
    const int w    = tid >> 5;
    const int lane = tid & 31;
    const int gid  = lane >> 2;   // group id (0..7)
    const int tig  = lane & 3;    // thread in group
    const int rowBase = blockIdx.x * 128;
    const int mBase = (w >> 2) * 64;   // warp M offset (0 or 64)
    const int nBase = (w & 3) * 32;    // warp N offset (0,32,64,96)

    float acc[4][4][4];
#pragma unroll
    for (int i = 0; i < 4; i++)
#pragma unroll
        for (int j = 0; j < 4; j++)
#pragma unroll
            for (int q = 0; q < 4; q++) acc[i][j][q] = 0.f;

    // per-thread load coordinates
    // X: 2 float4 per thread: f = tid + it*256; r=f>>2, k4=(f&3)*4
    // B: 1 uint4 per array: n = tid>>1, ch = tid&1 (8 k each)
    const int xr0 = tid >> 2,          xk0 = (tid & 3) * 4;
    const int xr1 = (tid + 256) >> 2,  xk1 = xk0;
    const int bn  = tid >> 1,          bch = tid & 1;

    // ---- prologue: stage step 0 into buffer 0 ----
    {
        const int k0 = 0;
        char* Ah = sm[0];            char* Al = sm[0] + 4096;
        char* Bh = sm[0] + 8192;     char* Bl = sm[0] + 12288;
#pragma unroll
        for (int it = 0; it < 2; it++) {
            int r  = it ? xr1 : xr0;
            int k4 = it ? xk1 : xk0;
            int grow = rowBase + r;
            float4 v = make_float4(0.f, 0.f, 0.f, 0.f);
            if (grow < M)
                v = *reinterpret_cast<const float4*>(&X[(size_t)grow * D_IN + k0 + k4]);
            float l0 = v.x - __bfloat162float(__float2bfloat16(v.x));
            float l1 = v.y - __bfloat162float(__float2bfloat16(v.y));
            float l2 = v.z - __bfloat162float(__float2bfloat16(v.z));
            float l3 = v.w - __bfloat162float(__float2bfloat16(v.w));
            uint2 hv = make_uint2(pack_bf2(v.x, v.y), pack_bf2(v.z, v.w));
            uint2 lv = make_uint2(pack_bf2(l0, l1), pack_bf2(l2, l3));
            uint32_t so = swz((uint32_t)r, (uint32_t)(k4 * 2));
            *reinterpret_cast<uint2*>(Ah + so) = hv;
            *reinterpret_cast<uint2*>(Al + so) = lv;
        }
        uint4 bhv = *reinterpret_cast<const uint4*>(&g_Whi[(size_t)bn * D_IN + k0 + bch * 8]);
        uint4 blv = *reinterpret_cast<const uint4*>(&g_Wlo[(size_t)bn * D_IN + k0 + bch * 8]);
        uint32_t so = swz((uint32_t)bn, (uint32_t)(bch * 16));
        *reinterpret_cast<uint4*>(Bh + so) = bhv;
        *reinterpret_cast<uint4*>(Bl + so) = blv;
    }
    __syncthreads();

    // ldmatrix source addresses (within-tile, buffer base added per step)
    const uint32_t aAddrOff = swz((uint32_t)(mBase + (lane & 15)), (uint32_t)(((lane >> 4) & 1) * 16));
    const uint32_t bAddrOff = swz((uint32_t)(nBase + (lane & 7)),  (uint32_t)(((lane >> 3) & 1) * 16));
    const uint32_t smBase   = smem_u32(sm);

    for (int c = 0; c < NSTEP; c++) {
        const int cur = c & 1;
        const bool has = (c + 1) < NSTEP;

        // ---- prefetch next tile into registers ----
        float4 xv0, xv1; uint4 bhv, blv;
        if (has) {
            const int k0 = (c + 1) * BK;
            int g0 = rowBase + xr0;
            int g1 = rowBase + xr1;
            xv0 = (g0 < M) ? *reinterpret_cast<const float4*>(&X[(size_t)g0 * D_IN + k0 + xk0])
                           : make_float4(0.f, 0.f, 0.f, 0.f);
            xv1 = (g1 < M) ? *reinterpret_cast<const float4*>(&X[(size_t)g1 * D_IN + k0 + xk1])
                           : make_float4(0.f, 0.f, 0.f, 0.f);
            bhv = *reinterpret_cast<const uint4*>(&g_Whi[(size_t)bn * D_IN + k0 + bch * 8]);
            blv = *reinterpret_cast<const uint4*>(&g_Wlo[(size_t)bn * D_IN + k0 + bch * 8]);
        }

        // ---- compute on current buffer ----
        const uint32_t base = smBase + cur * 16384;
        uint32_t ah[4][4], al[4][4], bh[4][2], bl[4][2];
#pragma unroll
        for (int mf = 0; mf < 4; mf++) {
            uint32_t a = base + aAddrOff + (uint32_t)(mf * 16 * 32);
            LDSM4(ah[mf][0], ah[mf][1], ah[mf][2], ah[mf][3], a);
            LDSM4(al[mf][0], al[mf][1], al[mf][2], al[mf][3], a + 4096);
        }
#pragma unroll
        for (int nf = 0; nf < 4; nf++) {
            uint32_t b = base + 8192 + bAddrOff + (uint32_t)(nf * 8 * 32);
            LDSM2(bh[nf][0], bh[nf][1], b);
            LDSM2(bl[nf][0], bl[nf][1], b + 4096);
        }
#pragma unroll
        for (int mf = 0; mf < 4; mf++)
#pragma unroll
            for (int nf = 0; nf < 4; nf++) {
                MMA16816(acc[mf][nf], ah[mf], bh[nf]);
                MMA16816(acc[mf][nf], ah[mf], bl[nf]);
                MMA16816(acc[mf][nf], al[mf], bh[nf]);
            }

        // ---- convert + store prefetched tile into other buffer ----
        if (has) {
            char* buf = sm[cur ^ 1];
            char* Ah = buf;            char* Al = buf + 4096;
            char* Bh = buf + 8192;     char* Bl = buf + 12288;
#pragma unroll
            for (int it = 0; it < 2; it++) {
                float4 v = it ? xv1 : xv0;
                int r  = it ? xr1 : xr0;
                int k4 = it ? xk1 : xk0;
                float l0 = v.x - __bfloat162float(__float2bfloat16(v.x));
                float l1 = v.y - __bfloat162float(__float2bfloat16(v.y));
                float l2 = v.z - __bfloat162float(__float2bfloat16(v.z));
                float l3 = v.w - __bfloat162float(__float2bfloat16(v.w));
                uint2 hv = make_uint2(pack_bf2(v.x, v.y), pack_bf2(v.z, v.w));
                uint2 lv = make_uint2(pack_bf2(l0, l1), pack_bf2(l2, l3));
                uint32_t so = swz((uint32_t)r, (uint32_t)(k4 * 2));
                *reinterpret_cast<uint2*>(Ah + so) = hv;
                *reinterpret_cast<uint2*>(Al + so) = lv;
            }
            uint32_t so = swz((uint32_t)bn, (uint32_t)(bch * 16));
            *reinterpret_cast<uint4*>(Bh + so) = bhv;
            *reinterpret_cast<uint4*>(Bl + so) = blv;
        }
        __syncthreads();
    }

    // ---- epilogue: write support ----
#pragma unroll
    for (int mf = 0; mf < 4; mf++) {
        int r0 = rowBase + mBase + mf * 16 + gid;
        int r1 = r0 + 8;
#pragma unroll
        for (int nf = 0; nf < 4; nf++) {
            int col = nBase + nf * 8 + tig * 2;
            if (r0 < M)
                *reinterpret_cast<float2*>(&g_support[(size_t)r0 * D_OUT + col]) =
                    make_float2(acc[mf][nf][0], acc[mf][nf][1]);
            if (r1 < M)
                *reinterpret_cast<float2*>(&g_support[(size_t)r1 * D_OUT + col]) =
                    make_float2(acc[mf][nf][2], acc[mf][nf][3]);
        }
    }
}

// ---------------------------------------------------------------------------
// Stage 2: rowptr[i] = lower_bound(edge_dst, i)
// ---------------------------------------------------------------------------
__global__ void rowptr_kernel(const int* __restrict__ edge_dst, int E, int M)
{
    int i = blockIdx.x * blockDim.x + threadIdx.x;
    if (i > M) return;
    int lo = 0, hi = E;
    while (lo < hi) {
        int mid = (lo + hi) >> 1;
        if (edge_dst[mid] < i) lo = mid + 1; else hi = mid;
    }
    g_rowptr[i] = lo;
}

// ---------------------------------------------------------------------------
// Stage 3: warp per node segment sum
// ---------------------------------------------------------------------------
__global__ __launch_bounds__(256)
void spmm_kernel(const int* __restrict__ edge_src,
                 const float* __restrict__ edge_val,
                 float* __restrict__ out, int M)
{
    const int warp = threadIdx.x >> 5;
    const int lane = threadIdx.x & 31;
    const int node = blockIdx.x * 8 + warp;
    if (node >= M) return;

    const int s = g_rowptr[node];
    const int e = g_rowptr[node + 1];

    float4 acc = make_float4(0.f, 0.f, 0.f, 0.f);
    const int col = lane * 4;

    int i = s;
    for (; i + 3 < e; i += 4) {
        int s0 = edge_src[i + 0], s1 = edge_src[i + 1];
        int s2 = edge_src[i + 2], s3 = edge_src[i + 3];
        float v0 = edge_val[i + 0], v1 = edge_val[i + 1];
        float v2 = edge_val[i + 2], v3 = edge_val[i + 3];
        float4 g0 = *reinterpret_cast<const float4*>(&g_support[(size_t)s0 * D_OUT + col]);
        float4 g1 = *reinterpret_cast<const float4*>(&g_support[(size_t)s1 * D_OUT + col]);
        float4 g2 = *reinterpret_cast<const float4*>(&g_support[(size_t)s2 * D_OUT + col]);
        float4 g3 = *reinterpret_cast<const float4*>(&g_support[(size_t)s3 * D_OUT + col]);
        acc.x = fmaf(g0.x, v0, acc.x); acc.y = fmaf(g0.y, v0, acc.y);
        acc.z = fmaf(g0.z, v0, acc.z); acc.w = fmaf(g0.w, v0, acc.w);
        acc.x = fmaf(g1.x, v1, acc.x); acc.y = fmaf(g1.y, v1, acc.y);
        acc.z = fmaf(g1.z, v1, acc.z); acc.w = fmaf(g1.w, v1, acc.w);
        acc.x = fmaf(g2.x, v2, acc.x); acc.y = fmaf(g2.y, v2, acc.y);
        acc.z = fmaf(g2.z, v2, acc.z); acc.w = fmaf(g2.w, v2, acc.w);
        acc.x = fmaf(g3.x, v3, acc.x); acc.y = fmaf(g3.y, v3, acc.y);
        acc.z = fmaf(g3.z, v3, acc.z); acc.w = fmaf(g3.w, v3, acc.w);
    }
    for (; i < e; ++i) {
        int sr = edge_src[i];
        float v = edge_val[i];
        float4 g = *reinterpret_cast<const float4*>(&g_support[(size_t)sr * D_OUT + col]);
        acc.x = fmaf(g.x, v, acc.x); acc.y = fmaf(g.y, v, acc.y);
        acc.z = fmaf(g.z, v, acc.z); acc.w = fmaf(g.w, v, acc.w);
    }

    *reinterpret_cast<float4*>(&out[(size_t)node * D_OUT + col]) = acc;
}

// ---------------------------------------------------------------------------
extern "C" void kernel_launch(void* const* d_in, const int* in_sizes, int n_in,
                              void* d_out, int out_size)
{
    const float* x        = (const float*)d_in[0];
    const int*   edge_src = (const int*)  d_in[1];
    const int*   edge_dst = (const int*)  d_in[2];
    const float* edge_val = (const float*)d_in[3];
    const float* weight   = (const float*)d_in[4];
    float*       out      = (float*)d_out;

    const int M = in_sizes[0] / D_IN;   // 50000
    const int E = in_sizes[1];          // 800000

    convw_kernel<<<(D_IN * D_OUT + 255) / 256, 256>>>(weight);
    gemm_mma_kernel<<<(M + 127) / 128, 256>>>(x, M);
    rowptr_kernel<<<(M + 1 + 255) / 256, 256>>>(edge_dst, E, M);
    spmm_kernel<<<(M + 7) / 8, 256>>>(edge_src, edge_val, out, M);
}

// round 5
// speedup vs baseline: 2.1497x; 1.4036x over previous
#include <cuda_runtime.h>
#include <cuda_fp16.h>
#include <cstdint>

// ---------------------------------------------------------------------------
// GraphConvolution: out = segment_sum( (X@W)[edge_src] * edge_val, edge_dst )
// Stage 0: W f32 [k][n] -> fp16, transposed to [n][k]
// Stage 1: GEMM via mma.sync m16n8k16 fp16 single-term (rel err ~3e-4)
// Stage 2: rowptr via binary search (edge_dst sorted)
// Stage 3: warp-per-node segment sum (no atomics)
// ---------------------------------------------------------------------------

#define MAX_NODES 50000
#define D_IN      512
#define D_OUT     128
#define BK        16
#define NSTEP     (D_IN / BK)   // 32

__device__ float g_support[(size_t)MAX_NODES * D_OUT];
__device__ int   g_rowptr[MAX_NODES + 1];
__device__ __align__(16) __half g_Wh[D_OUT * D_IN]; // [n][k]

// ------------------------------- helpers -----------------------------------
__device__ __forceinline__ uint32_t smem_u32(const void* p) {
    uint32_t a;
    asm("{ .reg .u64 t; cvta.to.shared.u64 t, %1; cvt.u32.u64 %0, t; }"
        : "=r"(a) : "l"(p));
    return a;
}
// swizzled byte offset within a [128 rows x 32B] tile
__device__ __forceinline__ uint32_t swz(uint32_t r, uint32_t c) {
    return r * 32 + ((((c >> 4) ^ (r >> 2)) & 1u) << 4) + (c & 15u);
}

#define LDSM4(r0, r1, r2, r3, a) \
    asm volatile("ldmatrix.sync.aligned.m8n8.x4.shared.b16 {%0,%1,%2,%3}, [%4];" \
        : "=r"(r0), "=r"(r1), "=r"(r2), "=r"(r3) : "r"(a))
#define LDSM2(r0, r1, a) \
    asm volatile("ldmatrix.sync.aligned.m8n8.x2.shared.b16 {%0,%1}, [%2];" \
        : "=r"(r0), "=r"(r1) : "r"(a))
#define MMA16816F16(c, a, b) \
    asm volatile("mma.sync.aligned.m16n8k16.row.col.f32.f16.f16.f32 " \
        "{%0,%1,%2,%3}, {%4,%5,%6,%7}, {%8,%9}, {%0,%1,%2,%3};" \
        : "+f"((c)[0]), "+f"((c)[1]), "+f"((c)[2]), "+f"((c)[3]) \
        : "r"((a)[0]), "r"((a)[1]), "r"((a)[2]), "r"((a)[3]), \
          "r"((b)[0]), "r"((b)[1]))

__device__ __forceinline__ uint32_t pack_h2(float lo, float hi) {
    __half2 h = __float22half2_rn(make_float2(lo, hi));
    return *reinterpret_cast<uint32_t*>(&h);
}

// ---------------------------------------------------------------------------
// Stage 0: convert + transpose W -> fp16 [n][k]
// ---------------------------------------------------------------------------
__global__ void convw_kernel(const float* __restrict__ W)
{
    int idx = blockIdx.x * blockDim.x + threadIdx.x;
    if (idx >= D_IN * D_OUT) return;
    int k = idx >> 7;
    int n = idx & 127;
    g_Wh[n * D_IN + k] = __float2half_rn(W[idx]);
}

// ---------------------------------------------------------------------------
// Stage 1: tensor-core GEMM via mma.sync fp16 (8 warps, 128x128 tile, BK=16)
// smem per buffer: A(4K) B(4K); 2 buffers = 16KB total -> 2 CTAs/SM
// ---------------------------------------------------------------------------
__global__ __launch_bounds__(256, 2)
void gemm_mma_kernel(const float* __restrict__ X, int M)
{
    __shared__ __align__(128) char sm[2][8192];

    const int tid  = threadIdx.x;
    const int w    = tid >> 5;
    const int lane = tid & 31;
    const int gid  = lane >> 2;
    const int tig  = lane & 3;
    const int rowBase = blockIdx.x * 128;
    const int mBase = (w >> 2) * 64;   // 0 or 64
    const int nBase = (w & 3) * 32;    // 0,32,64,96

    float acc[4][4][4];
#pragma unroll
    for (int i = 0; i < 4; i++)
#pragma unroll
        for (int j = 0; j < 4; j++)
#pragma unroll
            for (int q = 0; q < 4; q++) acc[i][j][q] = 0.f;

    // load coords: X: 2 float4/thread; B: 1 uint4/thread (8 halves)
    const int xr0 = tid >> 2,          xk0 = (tid & 3) * 4;
    const int xr1 = (tid + 256) >> 2;
    const int bn  = tid >> 1,          bch = tid & 1;

    // ---- prologue: stage step 0 ----
    {
        char* A = sm[0];
        char* B = sm[0] + 4096;
#pragma unroll
        for (int it = 0; it < 2; it++) {
            int r = it ? xr1 : xr0;
            int grow = rowBase + r;
            float4 v = make_float4(0.f, 0.f, 0.f, 0.f);
            if (grow < M)
                v = *reinterpret_cast<const float4*>(&X[(size_t)grow * D_IN + xk0]);
            uint2 hv = make_uint2(pack_h2(v.x, v.y), pack_h2(v.z, v.w));
            *reinterpret_cast<uint2*>(A + swz((uint32_t)r, (uint32_t)(xk0 * 2))) = hv;
        }
        uint4 bv = *reinterpret_cast<const uint4*>(&g_Wh[(size_t)bn * D_IN + bch * 8]);
        *reinterpret_cast<uint4*>(B + swz((uint32_t)bn, (uint32_t)(bch * 16))) = bv;
    }
    __syncthreads();

    const uint32_t aAddrOff = swz((uint32_t)(mBase + (lane & 15)), (uint32_t)(((lane >> 4) & 1) * 16));
    const uint32_t bAddrOff = swz((uint32_t)(nBase + (lane & 7)),  (uint32_t)(((lane >> 3) & 1) * 16));
    const uint32_t smBase   = smem_u32(sm);

    for (int c = 0; c < NSTEP; c++) {
        const int cur = c & 1;
        const bool has = (c + 1) < NSTEP;

        // prefetch next tile into registers
        float4 xv0, xv1; uint4 bv;
        if (has) {
            const int k0 = (c + 1) * BK;
            int g0 = rowBase + xr0;
            int g1 = rowBase + xr1;
            xv0 = (g0 < M) ? *reinterpret_cast<const float4*>(&X[(size_t)g0 * D_IN + k0 + xk0])
                           : make_float4(0.f, 0.f, 0.f, 0.f);
            xv1 = (g1 < M) ? *reinterpret_cast<const float4*>(&X[(size_t)g1 * D_IN + k0 + xk0])
                           : make_float4(0.f, 0.f, 0.f, 0.f);
            bv = *reinterpret_cast<const uint4*>(&g_Wh[(size_t)bn * D_IN + k0 + bch * 8]);
        }

        // compute on current buffer
        const uint32_t base = smBase + cur * 8192;
        uint32_t af[4][4], bf[4][2];
#pragma unroll
        for (int mf = 0; mf < 4; mf++) {
            uint32_t a = base + aAddrOff + (uint32_t)(mf * 16 * 32);
            LDSM4(af[mf][0], af[mf][1], af[mf][2], af[mf][3], a);
        }
#pragma unroll
        for (int nf = 0; nf < 4; nf++) {
            uint32_t b = base + 4096 + bAddrOff + (uint32_t)(nf * 8 * 32);
            LDSM2(bf[nf][0], bf[nf][1], b);
        }
#pragma unroll
        for (int mf = 0; mf < 4; mf++)
#pragma unroll
            for (int nf = 0; nf < 4; nf++)
                MMA16816F16(acc[mf][nf], af[mf], bf[nf]);

        // store prefetched tile into other buffer
        if (has) {
            char* A = sm[cur ^ 1];
            char* B = sm[cur ^ 1] + 4096;
#pragma unroll
            for (int it = 0; it < 2; it++) {
                float4 v = it ? xv1 : xv0;
                int r = it ? xr1 : xr0;
                uint2 hv = make_uint2(pack_h2(v.x, v.y), pack_h2(v.z, v.w));
                *reinterpret_cast<uint2*>(A + swz((uint32_t)r, (uint32_t)(xk0 * 2))) = hv;
            }
            *reinterpret_cast<uint4*>(B + swz((uint32_t)bn, (uint32_t)(bch * 16))) = bv;
        }
        __syncthreads();
    }

    // ---- epilogue ----
#pragma unroll
    for (int mf = 0; mf < 4; mf++) {
        int r0 = rowBase + mBase + mf * 16 + gid;
        int r1 = r0 + 8;
#pragma unroll
        for (int nf = 0; nf < 4; nf++) {
            int col = nBase + nf * 8 + tig * 2;
            if (r0 < M)
                *reinterpret_cast<float2*>(&g_support[(size_t)r0 * D_OUT + col]) =
                    make_float2(acc[mf][nf][0], acc[mf][nf][1]);
            if (r1 < M)
                *reinterpret_cast<float2*>(&g_support[(size_t)r1 * D_OUT + col]) =
                    make_float2(acc[mf][nf][2], acc[mf][nf][3]);
        }
    }
}

// ---------------------------------------------------------------------------
// Stage 2: rowptr[i] = lower_bound(edge_dst, i)
// ---------------------------------------------------------------------------
__global__ void rowptr_kernel(const int* __restrict__ edge_dst, int E, int M)
{
    int i = blockIdx.x * blockDim.x + threadIdx.x;
    if (i > M) return;
    int lo = 0, hi = E;
    while (lo < hi) {
        int mid = (lo + hi) >> 1;
        if (edge_dst[mid] < i) lo = mid + 1; else hi = mid;
    }
    g_rowptr[i] = lo;
}

// ---------------------------------------------------------------------------
// Stage 3: warp per node segment sum
// ---------------------------------------------------------------------------
__global__ __launch_bounds__(256)
void spmm_kernel(const int* __restrict__ edge_src,
                 const float* __restrict__ edge_val,
                 float* __restrict__ out, int M)
{
    const int warp = threadIdx.x >> 5;
    const int lane = threadIdx.x & 31;
    const int node = blockIdx.x * 8 + warp;
    if (node >= M) return;

    const int s = g_rowptr[node];
    const int e = g_rowptr[node + 1];

    float4 acc = make_float4(0.f, 0.f, 0.f, 0.f);
    const int col = lane * 4;

    int i = s;
    for (; i + 3 < e; i += 4) {
        int s0 = edge_src[i + 0], s1 = edge_src[i + 1];
        int s2 = edge_src[i + 2], s3 = edge_src[i + 3];
        float v0 = edge_val[i + 0], v1 = edge_val[i + 1];
        float v2 = edge_val[i + 2], v3 = edge_val[i + 3];
        float4 g0 = *reinterpret_cast<const float4*>(&g_support[(size_t)s0 * D_OUT + col]);
        float4 g1 = *reinterpret_cast<const float4*>(&g_support[(size_t)s1 * D_OUT + col]);
        float4 g2 = *reinterpret_cast<const float4*>(&g_support[(size_t)s2 * D_OUT + col]);
        float4 g3 = *reinterpret_cast<const float4*>(&g_support[(size_t)s3 * D_OUT + col]);
        acc.x = fmaf(g0.x, v0, acc.x); acc.y = fmaf(g0.y, v0, acc.y);
        acc.z = fmaf(g0.z, v0, acc.z); acc.w = fmaf(g0.w, v0, acc.w);
        acc.x = fmaf(g1.x, v1, acc.x); acc.y = fmaf(g1.y, v1, acc.y);
        acc.z = fmaf(g1.z, v1, acc.z); acc.w = fmaf(g1.w, v1, acc.w);
        acc.x = fmaf(g2.x, v2, acc.x); acc.y = fmaf(g2.y, v2, acc.y);
        acc.z = fmaf(g2.z, v2, acc.z); acc.w = fmaf(g2.w, v2, acc.w);
        acc.x = fmaf(g3.x, v3, acc.x); acc.y = fmaf(g3.y, v3, acc.y);
        acc.z = fmaf(g3.z, v3, acc.z); acc.w = fmaf(g3.w, v3, acc.w);
    }
    for (; i < e; ++i) {
        int sr = edge_src[i];
        float v = edge_val[i];
        float4 g = *reinterpret_cast<const float4*>(&g_support[(size_t)sr * D_OUT + col]);
        acc.x = fmaf(g.x, v, acc.x); acc.y = fmaf(g.y, v, acc.y);
        acc.z = fmaf(g.z, v, acc.z); acc.w = fmaf(g.w, v, acc.w);
    }

    *reinterpret_cast<float4*>(&out[(size_t)node * D_OUT + col]) = acc;
}

// ---------------------------------------------------------------------------
extern "C" void kernel_launch(void* const* d_in, const int* in_sizes, int n_in,
                              void* d_out, int out_size)
{
    const float* x        = (const float*)d_in[0];
    const int*   edge_src = (const int*)  d_in[1];
    const int*   edge_dst = (const int*)  d_in[2];
    const float* edge_val = (const float*)d_in[3];
    const float* weight   = (const float*)d_in[4];
    float*       out      = (float*)d_out;

    const int M = in_sizes[0] / D_IN;   // 50000
    const int E = in_sizes[1];          // 800000

    convw_kernel<<<(D_IN * D_OUT + 255) / 256, 256>>>(weight);
    gemm_mma_kernel<<<(M + 127) / 128, 256>>>(x, M);
    rowptr_kernel<<<(M + 1 + 255) / 256, 256>>>(edge_dst, E, M);
    spmm_kernel<<<(M + 7) / 8, 256>>>(edge_src, edge_val, out, M);
}

// round 6
// speedup vs baseline: 2.3319x; 1.0847x over previous
#include <cuda_runtime.h>
#include <cuda_fp16.h>
#include <cstdint>

// ---------------------------------------------------------------------------
// GraphConvolution: out = segment_sum( (X@W)[edge_src] * edge_val, edge_dst )
// Stage 0: W f32 [k][n] -> fp16, transposed to [n][k]
// Stage 1: GEMM via mma.sync m16n8k16 fp16; support stored as fp16
// Stage 2: rowptr via binary search (edge_dst sorted)
// Stage 3: warp-per-node segment sum, fp16 gathers, fp32 accum
// ---------------------------------------------------------------------------

#define MAX_NODES 50000
#define D_IN      512
#define D_OUT     128
#define BK        16
#define NSTEP     (D_IN / BK)   // 32

__device__ __align__(16) __half g_support_h[(size_t)MAX_NODES * D_OUT];
__device__ int   g_rowptr[MAX_NODES + 1];
__device__ __align__(16) __half g_Wh[D_OUT * D_IN]; // [n][k]

// ------------------------------- helpers -----------------------------------
__device__ __forceinline__ uint32_t smem_u32(const void* p) {
    uint32_t a;
    asm("{ .reg .u64 t; cvta.to.shared.u64 t, %1; cvt.u32.u64 %0, t; }"
        : "=r"(a) : "l"(p));
    return a;
}
// swizzled byte offset within a [128 rows x 32B] tile
__device__ __forceinline__ uint32_t swz(uint32_t r, uint32_t c) {
    return r * 32 + ((((c >> 4) ^ (r >> 2)) & 1u) << 4) + (c & 15u);
}

#define LDSM4(r0, r1, r2, r3, a) \
    asm volatile("ldmatrix.sync.aligned.m8n8.x4.shared.b16 {%0,%1,%2,%3}, [%4];" \
        : "=r"(r0), "=r"(r1), "=r"(r2), "=r"(r3) : "r"(a))
#define LDSM2(r0, r1, a) \
    asm volatile("ldmatrix.sync.aligned.m8n8.x2.shared.b16 {%0,%1}, [%2];" \
        : "=r"(r0), "=r"(r1) : "r"(a))
#define MMA16816F16(c, a, b) \
    asm volatile("mma.sync.aligned.m16n8k16.row.col.f32.f16.f16.f32 " \
        "{%0,%1,%2,%3}, {%4,%5,%6,%7}, {%8,%9}, {%0,%1,%2,%3};" \
        : "+f"((c)[0]), "+f"((c)[1]), "+f"((c)[2]), "+f"((c)[3]) \
        : "r"((a)[0]), "r"((a)[1]), "r"((a)[2]), "r"((a)[3]), \
          "r"((b)[0]), "r"((b)[1]))

__device__ __forceinline__ uint32_t pack_h2(float lo, float hi) {
    __half2 h = __float22half2_rn(make_float2(lo, hi));
    return *reinterpret_cast<uint32_t*>(&h);
}

// ---------------------------------------------------------------------------
// Stage 0: convert + transpose W -> fp16 [n][k]
// ---------------------------------------------------------------------------
__global__ void convw_kernel(const float* __restrict__ W)
{
    int idx = blockIdx.x * blockDim.x + threadIdx.x;
    if (idx >= D_IN * D_OUT) return;
    int k = idx >> 7;
    int n = idx & 127;
    g_Wh[n * D_IN + k] = __float2half_rn(W[idx]);
}

// ---------------------------------------------------------------------------
// Stage 1: tensor-core GEMM via mma.sync fp16 (8 warps, 128x128 tile, BK=16)
// ---------------------------------------------------------------------------
__global__ __launch_bounds__(256, 2)
void gemm_mma_kernel(const float* __restrict__ X, int M)
{
    __shared__ __align__(128) char sm[2][8192];

    const int tid  = threadIdx.x;
    const int w    = tid >> 5;
    const int lane = tid & 31;
    const int gid  = lane >> 2;
    const int tig  = lane & 3;
    const int rowBase = blockIdx.x * 128;
    const int mBase = (w >> 2) * 64;
    const int nBase = (w & 3) * 32;

    float acc[4][4][4];
#pragma unroll
    for (int i = 0; i < 4; i++)
#pragma unroll
        for (int j = 0; j < 4; j++)
#pragma unroll
            for (int q = 0; q < 4; q++) acc[i][j][q] = 0.f;

    const int xr0 = tid >> 2,          xk0 = (tid & 3) * 4;
    const int xr1 = (tid + 256) >> 2;
    const int bn  = tid >> 1,          bch = tid & 1;

    // ---- prologue: stage step 0 ----
    {
        char* A = sm[0];
        char* B = sm[0] + 4096;
#pragma unroll
        for (int it = 0; it < 2; it++) {
            int r = it ? xr1 : xr0;
            int grow = rowBase + r;
            float4 v = make_float4(0.f, 0.f, 0.f, 0.f);
            if (grow < M)
                v = *reinterpret_cast<const float4*>(&X[(size_t)grow * D_IN + xk0]);
            uint2 hv = make_uint2(pack_h2(v.x, v.y), pack_h2(v.z, v.w));
            *reinterpret_cast<uint2*>(A + swz((uint32_t)r, (uint32_t)(xk0 * 2))) = hv;
        }
        uint4 bv = *reinterpret_cast<const uint4*>(&g_Wh[(size_t)bn * D_IN + bch * 8]);
        *reinterpret_cast<uint4*>(B + swz((uint32_t)bn, (uint32_t)(bch * 16))) = bv;
    }
    __syncthreads();

    const uint32_t aAddrOff = swz((uint32_t)(mBase + (lane & 15)), (uint32_t)(((lane >> 4) & 1) * 16));
    const uint32_t bAddrOff = swz((uint32_t)(nBase + (lane & 7)),  (uint32_t)(((lane >> 3) & 1) * 16));
    const uint32_t smBase   = smem_u32(sm);

    for (int c = 0; c < NSTEP; c++) {
        const int cur = c & 1;
        const bool has = (c + 1) < NSTEP;

        float4 xv0, xv1; uint4 bv;
        if (has) {
            const int k0 = (c + 1) * BK;
            int g0 = rowBase + xr0;
            int g1 = rowBase + xr1;
            xv0 = (g0 < M) ? *reinterpret_cast<const float4*>(&X[(size_t)g0 * D_IN + k0 + xk0])
                           : make_float4(0.f, 0.f, 0.f, 0.f);
            xv1 = (g1 < M) ? *reinterpret_cast<const float4*>(&X[(size_t)g1 * D_IN + k0 + xk0])
                           : make_float4(0.f, 0.f, 0.f, 0.f);
            bv = *reinterpret_cast<const uint4*>(&g_Wh[(size_t)bn * D_IN + k0 + bch * 8]);
        }

        const uint32_t base = smBase + cur * 8192;
        uint32_t af[4][4], bf[4][2];
#pragma unroll
        for (int mf = 0; mf < 4; mf++) {
            uint32_t a = base + aAddrOff + (uint32_t)(mf * 16 * 32);
            LDSM4(af[mf][0], af[mf][1], af[mf][2], af[mf][3], a);
        }
#pragma unroll
        for (int nf = 0; nf < 4; nf++) {
            uint32_t b = base + 4096 + bAddrOff + (uint32_t)(nf * 8 * 32);
            LDSM2(bf[nf][0], bf[nf][1], b);
        }
#pragma unroll
        for (int mf = 0; mf < 4; mf++)
#pragma unroll
            for (int nf = 0; nf < 4; nf++)
                MMA16816F16(acc[mf][nf], af[mf], bf[nf]);

        if (has) {
            char* A = sm[cur ^ 1];
            char* B = sm[cur ^ 1] + 4096;
#pragma unroll
            for (int it = 0; it < 2; it++) {
                float4 v = it ? xv1 : xv0;
                int r = it ? xr1 : xr0;
                uint2 hv = make_uint2(pack_h2(v.x, v.y), pack_h2(v.z, v.w));
                *reinterpret_cast<uint2*>(A + swz((uint32_t)r, (uint32_t)(xk0 * 2))) = hv;
            }
            *reinterpret_cast<uint4*>(B + swz((uint32_t)bn, (uint32_t)(bch * 16))) = bv;
        }
        __syncthreads();
    }

    // ---- epilogue: write support as fp16 ----
#pragma unroll
    for (int mf = 0; mf < 4; mf++) {
        int r0 = rowBase + mBase + mf * 16 + gid;
        int r1 = r0 + 8;
#pragma unroll
        for (int nf = 0; nf < 4; nf++) {
            int col = nBase + nf * 8 + tig * 2;
            if (r0 < M)
                *reinterpret_cast<uint32_t*>(&g_support_h[(size_t)r0 * D_OUT + col]) =
                    pack_h2(acc[mf][nf][0], acc[mf][nf][1]);
            if (r1 < M)
                *reinterpret_cast<uint32_t*>(&g_support_h[(size_t)r1 * D_OUT + col]) =
                    pack_h2(acc[mf][nf][2], acc[mf][nf][3]);
        }
    }
}

// ---------------------------------------------------------------------------
// Stage 2: rowptr[i] = lower_bound(edge_dst, i)
// ---------------------------------------------------------------------------
__global__ void rowptr_kernel(const int* __restrict__ edge_dst, int E, int M)
{
    int i = blockIdx.x * blockDim.x + threadIdx.x;
    if (i > M) return;
    int lo = 0, hi = E;
    while (lo < hi) {
        int mid = (lo + hi) >> 1;
        if (edge_dst[mid] < i) lo = mid + 1; else hi = mid;
    }
    g_rowptr[i] = lo;
}

// ---------------------------------------------------------------------------
// Stage 3: warp per node segment sum; fp16 gathers (8B/lane), fp32 accum
// ---------------------------------------------------------------------------
__global__ __launch_bounds__(256)
void spmm_kernel(const int* __restrict__ edge_src,
                 const float* __restrict__ edge_val,
                 float* __restrict__ out, int M)
{
    const int warp = threadIdx.x >> 5;
    const int lane = threadIdx.x & 31;
    const int node = blockIdx.x * 8 + warp;
    if (node >= M) return;

    const int s = g_rowptr[node];
    const int e = g_rowptr[node + 1];

    float4 acc = make_float4(0.f, 0.f, 0.f, 0.f);
    const int col = lane * 4;
    const __half* supp = g_support_h;

    auto fma_row = [&](int src, float v) {
        uint2 q = *reinterpret_cast<const uint2*>(&supp[(size_t)src * D_OUT + col]);
        float2 f0 = __half22float2(*reinterpret_cast<__half2*>(&q.x));
        float2 f1 = __half22float2(*reinterpret_cast<__half2*>(&q.y));
        acc.x = fmaf(f0.x, v, acc.x);
        acc.y = fmaf(f0.y, v, acc.y);
        acc.z = fmaf(f1.x, v, acc.z);
        acc.w = fmaf(f1.y, v, acc.w);
    };

    int i = s;
    for (; i + 3 < e; i += 4) {
        int s0 = edge_src[i + 0], s1 = edge_src[i + 1];
        int s2 = edge_src[i + 2], s3 = edge_src[i + 3];
        float v0 = edge_val[i + 0], v1 = edge_val[i + 1];
        float v2 = edge_val[i + 2], v3 = edge_val[i + 3];
        // issue all 4 gathers before consuming (MLP)
        uint2 q0 = *reinterpret_cast<const uint2*>(&supp[(size_t)s0 * D_OUT + col]);
        uint2 q1 = *reinterpret_cast<const uint2*>(&supp[(size_t)s1 * D_OUT + col]);
        uint2 q2 = *reinterpret_cast<const uint2*>(&supp[(size_t)s2 * D_OUT + col]);
        uint2 q3 = *reinterpret_cast<const uint2*>(&supp[(size_t)s3 * D_OUT + col]);
        float2 a0 = __half22float2(*reinterpret_cast<__half2*>(&q0.x));
        float2 b0 = __half22float2(*reinterpret_cast<__half2*>(&q0.y));
        float2 a1 = __half22float2(*reinterpret_cast<__half2*>(&q1.x));
        float2 b1 = __half22float2(*reinterpret_cast<__half2*>(&q1.y));
        float2 a2 = __half22float2(*reinterpret_cast<__half2*>(&q2.x));
        float2 b2 = __half22float2(*reinterpret_cast<__half2*>(&q2.y));
        float2 a3 = __half22float2(*reinterpret_cast<__half2*>(&q3.x));
        float2 b3 = __half22float2(*reinterpret_cast<__half2*>(&q3.y));
        acc.x = fmaf(a0.x, v0, acc.x); acc.y = fmaf(a0.y, v0, acc.y);
        acc.z = fmaf(b0.x, v0, acc.z); acc.w = fmaf(b0.y, v0, acc.w);
        acc.x = fmaf(a1.x, v1, acc.x); acc.y = fmaf(a1.y, v1, acc.y);
        acc.z = fmaf(b1.x, v1, acc.z); acc.w = fmaf(b1.y, v1, acc.w);
        acc.x = fmaf(a2.x, v2, acc.x); acc.y = fmaf(a2.y, v2, acc.y);
        acc.z = fmaf(b2.x, v2, acc.z); acc.w = fmaf(b2.y, v2, acc.w);
        acc.x = fmaf(a3.x, v3, acc.x); acc.y = fmaf(a3.y, v3, acc.y);
        acc.z = fmaf(b3.x, v3, acc.z); acc.w = fmaf(b3.y, v3, acc.w);
    }
    for (; i < e; ++i)
        fma_row(edge_src[i], edge_val[i]);

    *reinterpret_cast<float4*>(&out[(size_t)node * D_OUT + col]) = acc;
}

// ---------------------------------------------------------------------------
extern "C" void kernel_launch(void* const* d_in, const int* in_sizes, int n_in,
                              void* d_out, int out_size)
{
    const float* x        = (const float*)d_in[0];
    const int*   edge_src = (const int*)  d_in[1];
    const int*   edge_dst = (const int*)  d_in[2];
    const float* edge_val = (const float*)d_in[3];
    const float* weight   = (const float*)d_in[4];
    float*       out      = (float*)d_out;

    const int M = in_sizes[0] / D_IN;   // 50000
    const int E = in_sizes[1];          // 800000

    convw_kernel<<<(D_IN * D_OUT + 255) / 256, 256>>>(weight);
    rowptr_kernel<<<(M + 1 + 255) / 256, 256>>>(edge_dst, E, M);
    gemm_mma_kernel<<<(M + 127) / 128, 256>>>(x, M);
    spmm_kernel<<<(M + 7) / 8, 256>>>(edge_src, edge_val, out, M);
}